// round 7
// baseline (speedup 1.0000x reference)
#include <cuda_runtime.h>

// ---------------- problem constants ----------------
#define VOCABN 35
#define PADV   34
#define HID    256
#define NSEQ   128
#define TT     256
#define TQn    255
#define NSG    8            // sequence groups (16 seqs each)
#define KP     65           // padded row stride in float4 units
#define ROWS7  1792
#define ARRN   (NSEQ*TQn*HID)

// scan decomposition: 128 CTAs; each CTA = one h-block (8 h) x TWO seq groups
#define HB2    8            // h indices per CTA
#define NHB    32           // h-blocks
#define NARR   32           // CTAs arriving per group barrier

// partials layout strides (floats): addr = nb*PS_N + s*PS_S + g7*4 + ks
// writers (lanes nb 0..7, sp 0..3): nb*1 + sp*8 mod 32 -> conflict-free
#define PS_N   577
#define PS_S   36
#define PS_SZ  4616

// ---------------- device scratch ----------------
__device__ float    g_ztab[VOCABN * ROWS7];
__device__ float    g_hbuf[2][NSEQ * HID];
__device__ unsigned g_cnt[NSG];
__device__ unsigned g_gen[NSG];

__device__ __forceinline__ void ffma2(unsigned long long &d,
                                      unsigned long long a,
                                      unsigned long long b) {
    asm("fma.rn.f32x2 %0, %1, %2, %0;" : "+l"(d) : "l"(a), "l"(b));
}
__device__ __forceinline__ float fsig(float x) {
    float e = __expf(-x);
    return __fdividef(1.0f, 1.0f + e);
}
__device__ __forceinline__ float ftanh_(float x) {
    float e = __expf(2.0f * x);
    return 1.0f - __fdividef(2.0f, e + 1.0f);
}

// ---------------- kernel A: Ztab = Emb @ W_x^T + b ----------------
__global__ void __launch_bounds__(256) ztab_kernel(const float* __restrict__ Emb,
                                                   const float* __restrict__ W,
                                                   const float* __restrict__ bias) {
    __shared__ float4 sE[7 * KP];
    const int t  = threadIdx.x;
    const int rb = blockIdx.x % 7;
    const int vg = blockIdx.x / 7;
    const int v0 = vg * 7;

    for (int f = t; f < 7 * 64; f += 256) {
        int j = f >> 6, kc = f & 63;
        sE[j * KP + kc] = ((const float4*)Emb)[(v0 + j) * 64 + kc];
    }
    __syncthreads();

    const int r = rb * 256 + t;
    float acc[7];
    const float bb = bias[r];
#pragma unroll
    for (int j = 0; j < 7; ++j) acc[j] = bb;

    const float4* wr = ((const float4*)W) + (size_t)r * 128;
#pragma unroll 4
    for (int kc = 0; kc < 64; ++kc) {
        float4 w = wr[kc];
#pragma unroll
        for (int j = 0; j < 7; ++j) {
            float4 e = sE[j * KP + kc];
            acc[j] += w.x * e.x + w.y * e.y + w.z * e.z + w.w * e.w;
        }
    }
#pragma unroll
    for (int j = 0; j < 7; ++j)
        g_ztab[(v0 + j) * ROWS7 + r] = acc[j];
}

// ---------------- kernel B: persistent reverse scan, 2 groups interleaved ----------------
#define OFF_W   0
#define OFF_H   (56 * KP * 16)                  // 58240
#define OFF_Z   (OFF_H + 16 * KP * 16)          // 74880
#define OFF_PS  (OFF_Z + VOCABN * 56 * 4)       // 82720
static const int SMEM_TOTAL = OFF_PS + PS_SZ * 4;   // 101184 B

struct PhaseCtx {
    const float4* sW4;
    float4*       sH4;
    const float*  sZ;
    float*        ps;
    const int*    ev;
    const float*  dtime;
    float*        out;
    int t, nb, sp, ks, hb;
    int s, h;          // gate role
    bool isg;          // t < 128
};

__device__ __forceinline__ void do_phase(const PhaseCtx &cx, int iter, int tq, int i,
                                         int q0, int sg, unsigned gen0,
                                         float &c_st, float &cb_st) {
    // ---- acquire: wait for previous iter's 32 arrivals of this group ----
    if (iter > 0) {
        if (cx.t == 0) {
            volatile unsigned* genp = (volatile unsigned*)&g_gen[sg];
            while (*genp - gen0 < (unsigned)iter) { }
            __threadfence();   // acquire; also invalidates L1 so h reload is fresh
        }
        __syncthreads();
    }

    // ---- prefetch event / dtime for gate role (latency hides under matvec) ----
    int v = 0; float dtv = 0.0f;
    if (cx.isg) {
        v   = __ldg(cx.ev    + (q0 + cx.s) * TT + i);
        dtv = __ldg(cx.dtime + (q0 + cx.s) * TT + i);
    }

    // ---- stage this group's hidden state into smem ----
    if (iter == 0) {
#pragma unroll
        for (int k = 0; k < 4; ++k) {
            int f = cx.t + k * 256;
            cx.sH4[(f >> 6) * KP + (f & 63)] = make_float4(0.f, 0.f, 0.f, 0.f);
        }
    } else {
        const float4* hsrc = (const float4*)(g_hbuf[iter & 1] + q0 * HID);
        float4 hv[4];
#pragma unroll
        for (int k = 0; k < 4; ++k) hv[k] = hsrc[cx.t + k * 256];
#pragma unroll
        for (int k = 0; k < 4; ++k) {
            int f = cx.t + k * 256;
            cx.sH4[(f >> 6) * KP + (f & 63)] = hv[k];
        }
    }
    __syncthreads();

    // ---- matvec: 7 gates x 2 seqs, quarter-K (fp32x2 packed FMA) ----
    const float4* sWrow = cx.sW4 + cx.nb * KP + cx.ks * 16;
    const float4* sHrow = cx.sH4 + (2 * cx.sp) * KP + cx.ks * 16;

    unsigned long long acc[7][2];
#pragma unroll
    for (int g7 = 0; g7 < 7; ++g7) { acc[g7][0] = 0ULL; acc[g7][1] = 0ULL; }

#pragma unroll
    for (int kc = 0; kc < 16; ++kc) {
        ulonglong2 h0 = ((const ulonglong2*)sHrow)[kc];
        ulonglong2 h1 = ((const ulonglong2*)(sHrow + KP))[kc];
#pragma unroll
        for (int g7 = 0; g7 < 7; ++g7) {
            ulonglong2 wv = ((const ulonglong2*)(sWrow + g7 * (HB2 * KP)))[kc];
            ffma2(acc[g7][0], wv.x, h0.x); ffma2(acc[g7][0], wv.y, h0.y);
            ffma2(acc[g7][1], wv.x, h1.x); ffma2(acc[g7][1], wv.y, h1.y);
        }
    }

    // ---- partials: conflict-free writes ----
    float* psw = cx.ps + cx.nb * PS_N + cx.ks;
#pragma unroll
    for (int g7 = 0; g7 < 7; ++g7)
#pragma unroll
        for (int j = 0; j < 2; ++j) {
            float2 p = *(float2*)&acc[g7][j];
            psw[(2 * cx.sp + j) * PS_S + g7 * 4] = p.x + p.y;
        }
    __syncthreads();

    // ---- gate role: reduce 4 K-quarters, add Ztab, cell math ----
    if (cx.isg) {
        const float* psr = cx.ps + cx.h * PS_N + cx.s * PS_S;
        float za[7];
#pragma unroll
        for (int g7 = 0; g7 < 7; ++g7) {
            float a0 = psr[g7 * 4 + 0] + psr[g7 * 4 + 1];
            float a1 = psr[g7 * 4 + 2] + psr[g7 * 4 + 3];
            za[g7] = cx.sZ[v * 56 + g7 * 8 + cx.h] + (a0 + a1);
        }

        float gi  = fsig(za[0]);
        float gf  = fsig(za[1]);
        float go  = fsig(za[2]);
        float gz  = ftanh_(za[3]);
        float gib = fsig(za[4]);
        float gfb = fsig(za[5]);
        float x6  = za[6];
        float gd  = fmaxf(x6, 0.0f) + log1pf(__expf(-fabsf(x6)));

        float cell   = gf * c_st + gi * gz;
        float cbar   = gfb * cb_st + gib * gz;
        float hminus = go * ftanh_(cell);
        float decay  = __expf(-gd * dtv);
        float cnew   = cbar + (cell - cbar) * decay;
        float hnew   = go * ftanh_(cnew);
        float m      = (v != PADV) ? 1.0f : 0.0f;
        cnew *= m;
        float cbarm = cbar * m;
        hnew *= m;
        c_st  = cnew;
        cb_st = cbarm;

        const int q  = q0 + cx.s;
        g_hbuf[(iter + 1) & 1][q * HID + cx.hb * HB2 + cx.h] = hnew;

        const int ob = (q * TQn + tq) * HID + cx.hb * HB2 + cx.h;
        cx.out[0 * ARRN + ob] = cell;
        cx.out[1 * ARRN + ob] = cbarm;
        cx.out[2 * ARRN + ob] = gd;
        cx.out[3 * ARRN + ob] = go;
        cx.out[4 * ARRN + ob] = hnew;
        cx.out[5 * ARRN + ob] = hminus;
    }
    __syncthreads();

    // ---- release: arrive at this group's barrier ----
    if (cx.t == 0) {
        __threadfence();
        unsigned old = atomicAdd(&g_cnt[sg], 1u);
        if (old == NARR - 1) {
            atomicExch(&g_cnt[sg], 0u);
            __threadfence();
            atomicAdd(&g_gen[sg], 1u);
        }
    }
}

__global__ void __launch_bounds__(256, 1)
scan_kernel(const int*   __restrict__ ev,
            const float* __restrict__ dtime,
            const float* __restrict__ W,
            float*       __restrict__ out) {
    extern __shared__ char smem[];
    PhaseCtx cx;
    cx.sW4   = (const float4*)(smem + OFF_W);
    cx.sH4   = (float4*)(smem + OFF_H);
    cx.sZ    = (const float*)(smem + OFF_Z);
    cx.ps    = (float*)(smem + OFF_PS);
    cx.ev    = ev;
    cx.dtime = dtime;
    cx.out   = out;

    const int t   = threadIdx.x;
    const int cta = blockIdx.x;
    cx.t  = t;
    cx.hb = cta & 31;                 // h-block 0..31
    const int gp  = cta >> 5;         // group pair 0..3
    const int sgA = gp * 2, sgB = gp * 2 + 1;
    const int q0A = sgA * 16, q0B = sgB * 16;

    cx.nb = t & 7;
    cx.sp = (t >> 3) & 7;
    cx.ks = t >> 6;
    cx.isg = (t < 128);
    cx.s = t >> 3;                    // gate role (valid for t<128)
    cx.h = t & 7;

    const unsigned gen0A = *((volatile unsigned*)&g_gen[sgA]);
    const unsigned gen0B = *((volatile unsigned*)&g_gen[sgB]);

    // ---- persistent W slice: rows g7*256 + hb*8 + j, cols 256..511 ----
    float4* sW4w = (float4*)(smem + OFF_W);
    for (int f = t; f < 56 * 64; f += 256) {
        int row = f >> 6, kc = f & 63;          // row = g7*8 + j
        int g7 = row >> 3, j = row & 7;
        int rg = g7 * HID + cx.hb * HB2 + j;
        sW4w[row * KP + kc] = ((const float4*)W)[(size_t)rg * 128 + 64 + kc];
    }
    // ---- persistent Ztab slice ----
    float* sZw = (float*)(smem + OFF_Z);
    for (int z = t; z < VOCABN * 56; z += 256) {
        int v = z / 56, rl = z % 56;
        int g7 = rl >> 3, j = rl & 7;
        sZw[z] = g_ztab[v * ROWS7 + g7 * HID + cx.hb * HB2 + j];
    }
    __syncthreads();

    float cA = 0.0f, cbA = 0.0f, cB = 0.0f, cbB = 0.0f;

    for (int iter = 0; iter < TQn; ++iter) {
        const int tq = TQn - 1 - iter;
        const int i  = tq + 1;
        do_phase(cx, iter, tq, i, q0A, sgA, gen0A, cA, cbA);
        do_phase(cx, iter, tq, i, q0B, sgB, gen0B, cB, cbB);
    }
}

// ---------------- launch ----------------
extern "C" void kernel_launch(void* const* d_in, const int* in_sizes, int n_in,
                              void* d_out, int out_size) {
    const int*   ev    = (const int*)  d_in[0];
    const float* dtime = (const float*)d_in[1];
    const float* Emb   = (const float*)d_in[2];
    const float* W     = (const float*)d_in[3];
    const float* bias  = (const float*)d_in[4];
    float* out = (float*)d_out;

    ztab_kernel<<<35, 256>>>(Emb, W, bias);

    cudaFuncSetAttribute(scan_kernel,
                         cudaFuncAttributeMaxDynamicSharedMemorySize, SMEM_TOTAL);
    scan_kernel<<<128, 256, SMEM_TOTAL>>>(ev, dtime, W, out);
}

// round 8
// speedup vs baseline: 1.6449x; 1.6449x over previous
#include <cuda_runtime.h>

// ---------------- problem constants ----------------
#define VOCABN 35
#define PADV   34
#define HID    256
#define NSEQ   128
#define TT     256
#define TQn    255
#define NSG    8            // sequence groups (16 seqs each)
#define KP     65           // padded row stride in float4 units (64 real + 1)
#define ROWS7  1792
#define ARRN   (NSEQ*TQn*HID)

// decomposition: 128 CTAs = 32 h-blocks (8 h) x 4 group-pairs.
// Each CTA: half-CTA 0 (threads 0-127, warps 0-3) runs group 2*gp,
//           half-CTA 1 (threads 128-255, warps 4-7) runs group 2*gp+1.
#define HB2    8            // h per CTA
#define NARR   32           // CTAs arriving per group barrier

// partials: per group, addr = slot(ks*4+sq)*PSS + (j*7+g7)*8 + nb
// PSS mod 32 == 8 -> writer banks sq*8+nb all distinct; reader banks j*24+h distinct.
#define PSS    232
#define PSG    (16*PSS)     // floats per group (3712)

// ---------------- device scratch ----------------
__device__ float    g_ztab[VOCABN * ROWS7];
__device__ float    g_hbuf[2][NSEQ * HID];
__device__ unsigned g_cnt[NSG];
__device__ unsigned g_gen[NSG];

__device__ __forceinline__ void ffma2(unsigned long long &d,
                                      unsigned long long a,
                                      unsigned long long b) {
    asm("fma.rn.f32x2 %0, %1, %2, %0;" : "+l"(d) : "l"(a), "l"(b));
}
__device__ __forceinline__ float fsig(float x) {
    float e = __expf(-x);
    return __fdividef(1.0f, 1.0f + e);
}
__device__ __forceinline__ float ftanh_(float x) {
    float e = __expf(2.0f * x);
    return 1.0f - __fdividef(2.0f, e + 1.0f);
}
#define BARS(id) asm volatile("bar.sync %0, 128;" :: "r"(id) : "memory")

// ---------------- kernel A: Ztab = Emb @ W_x^T + b ----------------
__global__ void __launch_bounds__(256) ztab_kernel(const float* __restrict__ Emb,
                                                   const float* __restrict__ W,
                                                   const float* __restrict__ bias) {
    __shared__ float4 sE[7 * KP];
    const int t  = threadIdx.x;
    const int rb = blockIdx.x % 7;
    const int vg = blockIdx.x / 7;
    const int v0 = vg * 7;

    for (int f = t; f < 7 * 64; f += 256) {
        int j = f >> 6, kc = f & 63;
        sE[j * KP + kc] = ((const float4*)Emb)[(v0 + j) * 64 + kc];
    }
    __syncthreads();

    const int r = rb * 256 + t;
    float acc[7];
    const float bb = bias[r];
#pragma unroll
    for (int j = 0; j < 7; ++j) acc[j] = bb;

    const float4* wr = ((const float4*)W) + (size_t)r * 128;
#pragma unroll 4
    for (int kc = 0; kc < 64; ++kc) {
        float4 w = wr[kc];
#pragma unroll
        for (int j = 0; j < 7; ++j) {
            float4 e = sE[j * KP + kc];
            acc[j] += w.x * e.x + w.y * e.y + w.z * e.z + w.w * e.w;
        }
    }
#pragma unroll
    for (int j = 0; j < 7; ++j)
        g_ztab[(v0 + j) * ROWS7 + r] = acc[j];
}

// ---------------- kernel B: persistent scan, warp-specialized 2 groups ----------------
#define OFF_W   0                               // 56*KP*16            = 58240
#define OFF_H   (56 * KP * 16)                  // 2 * 16*KP*16        = 33280
#define OFF_Z   (OFF_H + 2 * 16 * KP * 16)      // VOCABN*56*4         =  7840
#define OFF_PS  (OFF_Z + VOCABN * 56 * 4)       // 2 * PSG * 4         = 29696
static const int SMEM_TOTAL = OFF_PS + 2 * PSG * 4;   // 129056 B

__global__ void __launch_bounds__(256, 1)
scan_kernel(const int*   __restrict__ ev,
            const float* __restrict__ dtime,
            const float* __restrict__ W,
            float*       __restrict__ out) {
    extern __shared__ char smem[];
    const float4* sW4 = (const float4*)(smem + OFF_W);
    const float*  sZ  = (const float*) (smem + OFF_Z);

    const int t   = threadIdx.x;
    const int cta = blockIdx.x;
    const int hb  = cta & 31;          // h-block 0..31
    const int gp  = cta >> 5;          // group pair 0..3

    const int hf  = t >> 7;            // half: 0 -> warps 0-3, 1 -> warps 4-7
    const int tl  = t & 127;
    const int sg  = gp * 2 + hf;       // this half's sequence group
    const int q0  = sg * 16;
    const int bid = 1 + hf;            // named barrier id for this half

    const int nb = tl & 7;             // h index (compute role)
    const int sq = (tl >> 3) & 3;      // seq quad (4 seqs)
    const int ks = tl >> 5;            // K quarter
    const int s  = tl >> 3;            // gate role: sequence 0..15
    const int h  = tl & 7;             // gate role: h 0..7
    const int q  = q0 + s;

    float4* sH4g = (float4*)(smem + OFF_H) + hf * (16 * KP);
    float*  psg  = (float*)(smem + OFF_PS) + hf * PSG;

    // baseline generation (monotonic across graph replays)
    const unsigned gen0 = *((volatile unsigned*)&g_gen[sg]);

    // ---- persistent W slice (shared by both halves): rows g7*256 + hb*8 + j ----
    {
        float4* sW4w = (float4*)(smem + OFF_W);
        for (int f = t; f < 56 * 64; f += 256) {
            int row = f >> 6, kc = f & 63;          // row = g7*8 + j
            int g7 = row >> 3, j = row & 7;
            int rg = g7 * HID + hb * HB2 + j;
            sW4w[row * KP + kc] = ((const float4*)W)[(size_t)rg * 128 + 64 + kc];
        }
        float* sZw = (float*)(smem + OFF_Z);
        for (int z = t; z < VOCABN * 56; z += 256) {
            int v = z / 56, rl = z % 56;
            int g7 = rl >> 3, j = rl & 7;
            sZw[z] = g_ztab[v * ROWS7 + g7 * HID + hb * HB2 + j];
        }
    }
    __syncthreads();

    float c_st = 0.0f, cb_st = 0.0f;

    const float4* sWrow = sW4 + nb * KP + ks * 16;
    const float4* sHrow = sH4g + (4 * sq) * KP + ks * 16;
    float* psw = psg + (ks * 4 + sq) * PSS + nb;
    const float* psr = psg + (s >> 2) * PSS + h;   // + ks*928 per quarter

    for (int iter = 0; iter < TQn; ++iter) {
        const int tq = TQn - 1 - iter;
        const int i  = tq + 1;

        // prefetch inputs for gate role (independent of the barrier)
        const int   v   = __ldg(ev    + q * TT + i);
        const float dtv = __ldg(dtime + q * TT + i);

        // ---- acquire previous step of THIS group (other half keeps computing) ----
        if (iter > 0) {
            if (tl == 0) {
                volatile unsigned* genp = (volatile unsigned*)&g_gen[sg];
                while (*genp - gen0 < (unsigned)iter) { }
                __threadfence();
            }
            BARS(bid);
            const float4* hsrc = (const float4*)(g_hbuf[iter & 1] + q0 * HID);
            float4 hv[8];
#pragma unroll
            for (int k = 0; k < 8; ++k) hv[k] = hsrc[tl + k * 128];
#pragma unroll
            for (int k = 0; k < 8; ++k) {
                int f = tl + k * 128;
                sH4g[(f >> 6) * KP + (f & 63)] = hv[k];
            }
        } else {
#pragma unroll
            for (int k = 0; k < 8; ++k) {
                int f = tl + k * 128;
                sH4g[(f >> 6) * KP + (f & 63)] = make_float4(0.f, 0.f, 0.f, 0.f);
            }
        }
        BARS(bid);

        // ---- matvec: 7 gates x 4 seqs, quarter-K (fp32x2) ----
        unsigned long long acc[7][4];
#pragma unroll
        for (int g7 = 0; g7 < 7; ++g7)
#pragma unroll
            for (int j = 0; j < 4; ++j) acc[g7][j] = 0ULL;

#pragma unroll 4
        for (int kc = 0; kc < 16; ++kc) {
            ulonglong2 h0 = ((const ulonglong2*)(sHrow + 0 * KP))[kc];
            ulonglong2 h1 = ((const ulonglong2*)(sHrow + 1 * KP))[kc];
            ulonglong2 h2 = ((const ulonglong2*)(sHrow + 2 * KP))[kc];
            ulonglong2 h3 = ((const ulonglong2*)(sHrow + 3 * KP))[kc];
#pragma unroll
            for (int g7 = 0; g7 < 7; ++g7) {
                ulonglong2 wv = ((const ulonglong2*)(sWrow + g7 * (HB2 * KP)))[kc];
                ffma2(acc[g7][0], wv.x, h0.x); ffma2(acc[g7][0], wv.y, h0.y);
                ffma2(acc[g7][1], wv.x, h1.x); ffma2(acc[g7][1], wv.y, h1.y);
                ffma2(acc[g7][2], wv.x, h2.x); ffma2(acc[g7][2], wv.y, h2.y);
                ffma2(acc[g7][3], wv.x, h3.x); ffma2(acc[g7][3], wv.y, h3.y);
            }
        }

        // ---- partials (conflict-free: banks sq*8+nb distinct within warp) ----
#pragma unroll
        for (int g7 = 0; g7 < 7; ++g7)
#pragma unroll
            for (int j = 0; j < 4; ++j) {
                float2 p = *(float2*)&acc[g7][j];
                psw[(j * 7 + g7) * 8] = p.x + p.y;
            }
        BARS(bid);

        // ---- gate role: reduce 4 K-quarters, add Ztab, cell math ----
        float za[7];
#pragma unroll
        for (int g7 = 0; g7 < 7; ++g7) {
            const int bo = ((s & 3) * 7 + g7) * 8;
            float a0 = psr[bo] + psr[bo + 928];
            float a1 = psr[bo + 1856] + psr[bo + 2784];
            za[g7] = sZ[v * 56 + g7 * 8 + h] + (a0 + a1);
        }

        float gi  = fsig(za[0]);
        float gf  = fsig(za[1]);
        float go  = fsig(za[2]);
        float gz  = ftanh_(za[3]);
        float gib = fsig(za[4]);
        float gfb = fsig(za[5]);
        float x6  = za[6];
        float gd  = fmaxf(x6, 0.0f) + log1pf(__expf(-fabsf(x6)));

        float cell   = gf * c_st + gi * gz;
        float cbar   = gfb * cb_st + gib * gz;
        float hminus = go * ftanh_(cell);
        float decay  = __expf(-gd * dtv);
        float cnew   = cbar + (cell - cbar) * decay;
        float hnew   = go * ftanh_(cnew);
        float m      = (v != PADV) ? 1.0f : 0.0f;
        cnew *= m;
        float cbarm = cbar * m;
        hnew *= m;
        c_st  = cnew;
        cb_st = cbarm;

        // publish hidden state for next step
        g_hbuf[(iter + 1) & 1][q * HID + hb * HB2 + h] = hnew;
        BARS(bid);

        // ---- release this group's barrier, then overlap output stores ----
        if (tl == 0) {
            __threadfence();
            unsigned old = atomicAdd(&g_cnt[sg], 1u);
            if (old == NARR - 1) {
                atomicExch(&g_cnt[sg], 0u);
                __threadfence();
                atomicAdd(&g_gen[sg], 1u);
            }
        }

        const int ob = (q * TQn + tq) * HID + hb * HB2 + h;
        out[0 * ARRN + ob] = cell;
        out[1 * ARRN + ob] = cbarm;
        out[2 * ARRN + ob] = gd;
        out[3 * ARRN + ob] = go;
        out[4 * ARRN + ob] = hnew;
        out[5 * ARRN + ob] = hminus;
    }
}

// ---------------- launch ----------------
extern "C" void kernel_launch(void* const* d_in, const int* in_sizes, int n_in,
                              void* d_out, int out_size) {
    const int*   ev    = (const int*)  d_in[0];
    const float* dtime = (const float*)d_in[1];
    const float* Emb   = (const float*)d_in[2];
    const float* W     = (const float*)d_in[3];
    const float* bias  = (const float*)d_in[4];
    float* out = (float*)d_out;

    ztab_kernel<<<35, 256>>>(Emb, W, bias);

    cudaFuncSetAttribute(scan_kernel,
                         cudaFuncAttributeMaxDynamicSharedMemorySize, SMEM_TOTAL);
    scan_kernel<<<128, 256, SMEM_TOTAL>>>(ev, dtime, W, out);
}